// round 16
// baseline (speedup 1.0000x reference)
#include <cuda_runtime.h>
#include <stdint.h>

// Problem shape (static)
#define B 32
#define L 4
#define S 512
#define D 768
#define D2 (D / 2)      // 384 float2 columns
#define G 24            // NUM_SEGMENTS
#define NCHUNK 12       // 3 dslices * 12 chunks * 32 batches = 1152 CTAs = one wave @ occ 8
#define TPC (S / NCHUNK)

// Output layout (float32, tuple-order concat):
//   word [B,S,D] | sent [B,D] | seg [B,G,D] | mask [B,G]
#define OFF_SENT ((size_t)B * S * D)
#define OFF_SEG  (OFF_SENT + (size_t)B * D)
#define OFF_MASK (OFF_SEG + (size_t)B * G * D)
// region accumulated with atomics -> must start at zero: sent + seg (contiguous)
#define ZERO_N   ((size_t)B * D + (size_t)B * G * D)

__device__ __forceinline__ void f2add(float2& a, const float2& b) {
    a.x += b.x; a.y += b.y;
}

// grid: (3 dslices * NCHUNK, 32 batches), block: 128 threads (each owns one float2 column)
__global__ void __launch_bounds__(128, 8)
bert_agg_kernel(const float2* __restrict__ emb,
                const int*    __restrict__ tg,
                const int*    __restrict__ sg,
                float*        __restrict__ out)
{
    const int b      = blockIdx.y;
    const int chunk  = blockIdx.x / 3;
    const int dslice = blockIdx.x % 3;
    const int d2     = dslice * 128 + threadIdx.x;   // float2 column index (0..383)

    __shared__ int s_tg[S];
    __shared__ int s_sg[S];
    for (int i = threadIdx.x; i < S; i += 128) {
        s_tg[i] = tg[b * S + i];
        s_sg[i] = sg[b * S + i];
    }
    __syncthreads();

    // ---- chunk bounds snapped to WORD-run boundaries (block-uniform) ----
    int ts = chunk * TPC;
    while (ts > 0 && ts < S && s_tg[ts] == s_tg[ts - 1]) ++ts;
    int te;
    if (chunk == NCHUNK - 1) {
        te = S;
    } else {
        te = (chunk + 1) * TPC;
        while (te < S && s_tg[te] == s_tg[te - 1]) ++te;
    }

    // 32-bit offsets (max index < 2^25)
    const int     LS2  = S * D2;                      // layer stride in float2
    const float2* ep   = emb + (b * L * S * D2) + d2;
    float2*       wout = (float2*)out + (b * S * D2) + d2;
    float*        gout = out + OFF_SEG + (b * G * D) + d2 * 2;

    const float2 zero2 = make_float2(0.f, 0.f);

    if (ts < te) {
        // leading word gap (only the chunk starting at token 0)
        if (ts == 0) {
            const int firstw = s_tg[0];
            for (int z = 0; z < firstw; ++z) wout[z * D2] = zero2;
        }

        float2 sent   = zero2;
        int    cur_g  = s_tg[ts];
        float2 wacc   = zero2;
        int    cur_sg = s_sg[cur_g];
        float2 gacc   = zero2;

        // ---- streaming: 4 tokens x 4 layers in flight (16 independent LDG.64) ----
        float2 v0[4], v1[4], v2[4], v3[4];
#pragma unroll
        for (int i = 0; i < 4; ++i) {
            const int t = (ts + i < S) ? (ts + i) : (S - 1);
            const float2* p = ep + t * D2;
            v0[i] = p[0];
            v1[i] = p[LS2];
            v2[i] = p[2 * LS2];
            v3[i] = p[3 * LS2];
        }

#pragma unroll 1
        for (int tc = ts; tc < te; tc += 4) {
            float2 e[4];
#pragma unroll
            for (int i = 0; i < 4; ++i) {
                float2 s0 = v0[i]; f2add(s0, v1[i]);
                float2 s1 = v2[i]; f2add(s1, v3[i]);
                f2add(s0, s1);
                e[i] = s0;
            }

            const int tn = tc + 4;
            if (tn < te) {
#pragma unroll
                for (int i = 0; i < 4; ++i) {
                    const int t = (tn + i < S) ? (tn + i) : (S - 1);
                    const float2* p = ep + t * D2;
                    v0[i] = p[0];
                    v1[i] = p[LS2];
                    v2[i] = p[2 * LS2];
                    v3[i] = p[3 * LS2];
                }
            }

            const int n = te - tc;
#pragma unroll
            for (int i = 0; i < 4; ++i) {
                if (i < n) {
                    const int g = s_tg[tc + i];
                    if (g != cur_g) {
                        // flush completed word run (chunk-exclusive)
                        wout[cur_g * D2] = wacc;
                        const int mysg = s_sg[cur_g];
                        if (mysg != cur_sg) {
                            float* gp = gout + cur_sg * D;
                            if (gacc.x != 0.f || gacc.y != 0.f) {
                                atomicAdd(gp,     gacc.x);
                                atomicAdd(gp + 1, gacc.y);
                            }
                            gacc   = zero2;
                            cur_sg = mysg;
                        }
                        f2add(gacc, wacc);
                        // zero skipped word slots interior to this chunk's range
                        for (int z = cur_g + 1; z < g; ++z)
                            wout[z * D2] = zero2;
                        wacc  = zero2;
                        cur_g = g;
                    }
                    f2add(wacc, e[i]);
                    f2add(sent, e[i]);
                }
            }
        }

        // ---- final flushes ----
        wout[cur_g * D2] = wacc;
        {
            const int mysg = s_sg[cur_g];
            if (mysg != cur_sg) {
                float* gp = gout + cur_sg * D;
                if (gacc.x != 0.f || gacc.y != 0.f) {
                    atomicAdd(gp,     gacc.x);
                    atomicAdd(gp + 1, gacc.y);
                }
                gacc   = zero2;
                cur_sg = mysg;
            }
            f2add(gacc, wacc);
        }
        {
            float* gp = gout + cur_sg * D;
            atomicAdd(gp,     gacc.x);
            atomicAdd(gp + 1, gacc.y);
        }

        // trailing word gap owned by this chunk
        {
            const int nextw = (te < S) ? s_tg[te] : S;
            for (int z = cur_g + 1; z < nextw; ++z)
                wout[z * D2] = zero2;
        }

        // sentence partial: mean over 512 padded word slots == total sum / 512
        {
            float* sp = out + OFF_SENT + b * D + d2 * 2;
            atomicAdd(sp,     sent.x * (1.0f / 512.0f));
            atomicAdd(sp + 1, sent.y * (1.0f / 512.0f));
        }
    }

    // seg_mask (sorted segment_ids -> max is last element); one CTA per batch
    if (blockIdx.x == 0 && threadIdx.x < G) {
        const int seg_num = s_sg[S - 1] + 1;
        out[OFF_MASK + (size_t)b * G + threadIdx.x] =
            (threadIdx.x >= seg_num) ? 1.0f : 0.0f;
    }
}

extern "C" void kernel_launch(void* const* d_in, const int* in_sizes, int n_in,
                              void* d_out, int out_size)
{
    const float2* emb = (const float2*)d_in[0];  // embeddings      [B,L,S,D] f32
    const int*    tg  = (const int*)  d_in[1];   // token_group_ids [B,S] i32
    const int*    sg  = (const int*)  d_in[2];   // segment_ids     [B,S] i32
    float*        out = (float*)d_out;

    // zero the atomically-accumulated region (sent + seg) via a memset node
    cudaMemsetAsync(out + OFF_SENT, 0, ZERO_N * sizeof(float));

    dim3 grid(3 * NCHUNK, B);   // (36, 32) = 1152 CTAs = one wave @ occ 8
    bert_agg_kernel<<<grid, 128>>>(emb, tg, sg, out);
}

// round 17
// speedup vs baseline: 1.1205x; 1.1205x over previous
#include <cuda_runtime.h>
#include <stdint.h>

// Problem shape (static)
#define B 32
#define L 4
#define S 512
#define D 768
#define G 24        // NUM_SEGMENTS
#define NCHUNK 6
#define TPC (S / NCHUNK)

// Output layout (float32, tuple-order concat):
//   word [B,S,D] | sent [B,D] | seg [B,G,D] | mask [B,G]
#define OFF_SENT ((size_t)B * S * D)
#define OFF_SEG  (OFF_SENT + (size_t)B * D)
#define OFF_MASK (OFF_SEG + (size_t)B * G * D)
// region accumulated with atomics -> must start at zero: sent + seg (contiguous)
#define ZERO_N   ((size_t)B * D + (size_t)B * G * D)

// grid: (6 dslices * NCHUNK, 32 batches), block: 128 threads (1 d column each)
__global__ void __launch_bounds__(128, 8)
bert_agg_kernel(const float* __restrict__ emb,
                const int*   __restrict__ tg,
                const int*   __restrict__ sg,
                float*       __restrict__ out)
{
    const int b      = blockIdx.y;
    const int chunk  = blockIdx.x / 6;
    const int dslice = blockIdx.x % 6;
    const int d      = dslice * 128 + threadIdx.x;

    __shared__ int s_tg[S];
    __shared__ int s_sg[S];
    for (int i = threadIdx.x; i < S; i += 128) {
        s_tg[i] = tg[b * S + i];
        s_sg[i] = sg[b * S + i];
    }
    __syncthreads();

    // ---- chunk bounds, snapped to word-run boundaries (block-uniform) ----
    int ts = chunk * TPC;
    while (ts > 0 && ts < S && s_tg[ts] == s_tg[ts - 1]) ++ts;
    int te;
    if (chunk == NCHUNK - 1) {
        te = S;
    } else {
        te = (chunk + 1) * TPC;
        while (te < S && s_tg[te] == s_tg[te - 1]) ++te;
    }

    // 32-bit offsets (max index < 2^26)
    const int    LS  = S * D;                 // layer stride in floats
    const float* ep  = emb + (b * L * S * D) + d;
    float*      wout = out + (b * S * D) + d;
    float*      gout = out + OFF_SEG + (b * G * D) + d;

    // ---- GLOBAL trailing-zero tail, distributed round-robin over all chunks ----
    // word slots beyond the last word id (~40% of word output!) used to be
    // written by the last chunk alone, making it the makespan. Every CTA zeroes
    // the slots z in [last_word+1, S) with z % NCHUNK == chunk.
    {
        const int tail0 = s_tg[S - 1] + 1;
        for (int z = tail0 + chunk; z < S; z += NCHUNK)
            wout[z * D] = 0.f;
    }

    if (ts < te) {
        // leading word gap (only the chunk starting at token 0)
        if (ts == 0) {
            const int firstw = s_tg[0];
            for (int z = 0; z < firstw; ++z) wout[z * D] = 0.f;
        }

        float sent   = 0.f;
        int   cur_g  = s_tg[ts];
        float wacc   = 0.f;
        int   cur_sg = s_sg[cur_g];
        float gacc   = 0.f;

        // ---- streaming: 4 tokens x 4 layers in flight (16 independent LDG.32) ----
        float v0[4], v1[4], v2[4], v3[4];
#pragma unroll
        for (int i = 0; i < 4; ++i) {
            const int t = (ts + i < S) ? (ts + i) : (S - 1);
            const float* p = ep + t * D;
            v0[i] = p[0];
            v1[i] = p[LS];
            v2[i] = p[2 * LS];
            v3[i] = p[3 * LS];
        }

#pragma unroll 1
        for (int tc = ts; tc < te; tc += 4) {
            float e[4];
#pragma unroll
            for (int i = 0; i < 4; ++i)
                e[i] = (v0[i] + v1[i]) + (v2[i] + v3[i]);

            const int tn = tc + 4;
            if (tn < te) {
#pragma unroll
                for (int i = 0; i < 4; ++i) {
                    const int t = (tn + i < S) ? (tn + i) : (S - 1);
                    const float* p = ep + t * D;
                    v0[i] = p[0];
                    v1[i] = p[LS];
                    v2[i] = p[2 * LS];
                    v3[i] = p[3 * LS];
                }
            }

            const int n = te - tc;
#pragma unroll
            for (int i = 0; i < 4; ++i) {
                if (i < n) {
                    const int g = s_tg[tc + i];
                    if (g != cur_g) {
                        // flush completed word run (owned exclusively by this chunk)
                        wout[cur_g * D] = wacc;
                        const int mysg = s_sg[cur_g];
                        if (mysg != cur_sg) {
                            if (gacc != 0.f) atomicAdd(&gout[cur_sg * D], gacc);
                            gacc   = 0.f;
                            cur_sg = mysg;
                        }
                        gacc += wacc;
                        // zero skipped word slots interior to this chunk's range
                        for (int z = cur_g + 1; z < g; ++z)
                            wout[z * D] = 0.f;
                        wacc  = 0.f;
                        cur_g = g;
                    }
                    wacc += e[i];
                    sent += e[i];
                }
            }
        }

        // ---- final flushes ----
        wout[cur_g * D] = wacc;
        {
            const int mysg = s_sg[cur_g];
            if (mysg != cur_sg) {
                if (gacc != 0.f) atomicAdd(&gout[cur_sg * D], gacc);
                gacc   = 0.f;
                cur_sg = mysg;
            }
            gacc += wacc;
        }
        atomicAdd(&gout[cur_sg * D], gacc);

        // trailing word gap up to the NEXT chunk's first word only
        // (the global tail past s_tg[S-1] is handled round-robin above)
        {
            const int nextw = (te < S) ? s_tg[te] : (s_tg[S - 1] + 1);
            for (int z = cur_g + 1; z < nextw; ++z)
                wout[z * D] = 0.f;
        }

        // sentence partial: mean over 512 padded word slots == total sum / 512
        atomicAdd(&out[OFF_SENT + b * D + d], sent * (1.0f / 512.0f));
    }

    // seg_mask (sorted segment_ids -> max is last element); one CTA per batch
    if (blockIdx.x == 0 && threadIdx.x < G) {
        const int seg_num = s_sg[S - 1] + 1;
        out[OFF_MASK + (size_t)b * G + threadIdx.x] =
            (threadIdx.x >= seg_num) ? 1.0f : 0.0f;
    }
}

extern "C" void kernel_launch(void* const* d_in, const int* in_sizes, int n_in,
                              void* d_out, int out_size)
{
    const float* emb = (const float*)d_in[0];   // embeddings      [B,L,S,D] f32
    const int*   tg  = (const int*)  d_in[1];   // token_group_ids [B,S] i32
    const int*   sg  = (const int*)  d_in[2];   // segment_ids     [B,S] i32
    float*       out = (float*)d_out;

    // zero the atomically-accumulated region (sent + seg) via a memset node
    cudaMemsetAsync(out + OFF_SENT, 0, ZERO_N * sizeof(float));

    dim3 grid(6 * NCHUNK, B);   // (36, 32) = 1152 CTAs ~= one wave at occ 8
    bert_agg_kernel<<<grid, 128>>>(emb, tg, sg, out);
}